// round 10
// baseline (speedup 1.0000x reference)
#include <cuda_runtime.h>

// SCVC: out[n, g*OG+o, p, q] = C[g,o]*x[n,g,p]*y[n,g,q] + a[n,g,o,p] + b[n,g,o,q]
//   a[p] = wA0*x[p-1] + wA1*x[p+1]  (zero boundary)
//   b[q] = wB0*y[q-1] + wB1*y[q+1]  (zero boundary)
// Shapes: N=8, G=8, OG=16, DX=DY=256. Output = 256 MiB fp32 -> HBM-store floor.
// R10: 256-bit stores (st.global.cs.v8.f32, sm_100+). One warp stores a full
// 1024B row per instruction; halves l1tex store wavefronts vs STG.128.

#define N_  8
#define G_  8
#define OG_ 16
#define DX_ 256
#define DY_ 256
#define PT  16   // p-rows per block

__device__ __forceinline__ void stg256_cs(float* p, const float v[8]) {
    asm volatile(
        "st.global.cs.v8.f32 [%0], {%1,%2,%3,%4,%5,%6,%7,%8};"
        :: "l"(p),
           "f"(v[0]), "f"(v[1]), "f"(v[2]), "f"(v[3]),
           "f"(v[4]), "f"(v[5]), "f"(v[6]), "f"(v[7])
        : "memory");
}

__global__ __launch_bounds__(256) void scvc_kernel(
    const float* __restrict__ x,   // (N, G, DX)
    const float* __restrict__ y,   // (N, G, DY)
    const float* __restrict__ C,   // (G, OG)
    const float* __restrict__ wA,  // (G, OG, 2)
    const float* __restrict__ wB,  // (G, OG, 2)
    float* __restrict__ out)       // (N, G*OG, DX, DY)
{
    __shared__ float  sy[DY_];
    __shared__ float2 ssap[PT];   // (s = C*x[p], ap = wA0*x[p-1] + wA1*x[p+1])

    const int b  = blockIdx.x;
    const int pt = b & 15;            // DX_/PT = 16 tiles
    const int o  = (b >> 4) & 15;     // OG_ = 16
    const int g  = (b >> 8) & 7;      // G_  = 8
    const int n  = b >> 11;           // N_  = 8

    const int tid = threadIdx.x;
    const int ng = n * G_ + g;
    const int go = g * OG_ + o;

    // Stage y row.
    sy[tid] = y[ng * DY_ + tid];

    // Per-row scalars (independent of sy) — before the single barrier.
    if (tid < PT) {
        const float* __restrict__ xrow = x + ng * DX_;
        const float Cgo = C[go];
        const float wA0 = wA[go * 2 + 0];
        const float wA1 = wA[go * 2 + 1];
        const int p = pt * PT + tid;
        const float xp = xrow[p];
        const float xl = (p > 0)       ? xrow[p - 1] : 0.0f;
        const float xr = (p < DX_ - 1) ? xrow[p + 1] : 0.0f;
        ssap[tid] = make_float2(Cgo * xp, wA0 * xl + wA1 * xr);
    }
    const float wB0 = wB[go * 2 + 0];
    const float wB1 = wB[go * 2 + 1];
    __syncthreads();

    // Thread layout: r = row-within-8 (8 rows/pass), c8 = 8-float column (32/row).
    const int r  = tid >> 5;
    const int c8 = tid & 31;
    const int q0 = c8 * 8;

    // y fragment (8 values) + halo; b[q] computed in registers.
    float yv[8];
    {
        const float4 ylo = reinterpret_cast<const float4*>(sy)[c8 * 2 + 0];
        const float4 yhi = reinterpret_cast<const float4*>(sy)[c8 * 2 + 1];
        yv[0] = ylo.x; yv[1] = ylo.y; yv[2] = ylo.z; yv[3] = ylo.w;
        yv[4] = yhi.x; yv[5] = yhi.y; yv[6] = yhi.z; yv[7] = yhi.w;
    }
    const float yl = (q0 > 0)        ? sy[q0 - 1] : 0.0f;
    const float yr = (q0 + 8 < DY_)  ? sy[q0 + 8] : 0.0f;

    float bv[8];
    bv[0] = wB0 * yl + wB1 * yv[1];
    #pragma unroll
    for (int i = 1; i < 7; ++i)
        bv[i] = wB0 * yv[i - 1] + wB1 * yv[i + 1];
    bv[7] = wB0 * yv[6] + wB1 * yr;

    float* __restrict__ obase =
        out + ((size_t)ng * OG_ + o) * (size_t)(DX_ * DY_);

    #pragma unroll
    for (int it = 0; it < PT / 8; ++it) {
        const int p = pt * PT + it * 8 + r;
        const float2 sa = ssap[it * 8 + r];  // broadcast LDS.64
        const float s  = sa.x;
        const float ap = sa.y;

        float v[8];
        #pragma unroll
        for (int i = 0; i < 8; ++i)
            v[i] = fmaf(s, yv[i], ap + bv[i]);

        stg256_cs(obase + (size_t)p * DY_ + q0, v);
    }
}

extern "C" void kernel_launch(void* const* d_in, const int* in_sizes, int n_in,
                              void* d_out, int out_size)
{
    const float* x  = (const float*)d_in[0];
    const float* y  = (const float*)d_in[1];
    const float* C  = (const float*)d_in[2];
    const float* wA = (const float*)d_in[3];
    const float* wB = (const float*)d_in[4];
    float* out = (float*)d_out;

    const int nblocks = N_ * G_ * OG_ * (DX_ / PT);  // 16384
    scvc_kernel<<<nblocks, 256>>>(x, y, C, wA, wB, out);
}

// round 13
// speedup vs baseline: 1.2598x; 1.2598x over previous
#include <cuda_runtime.h>

// SCVC: out[n, g*OG+o, p, q] = C[g,o]*x[n,g,p]*y[n,g,q] + a[n,g,o,p] + b[n,g,o,q]
//   a[p] = wA0*x[p-1] + wA1*x[p+1]  (zero boundary)
//   b[q] = wB0*y[q-1] + wB1*y[q+1]  (zero boundary)
// Shapes: N=8, G=8, OG=16, DX=DY=256. Output = 256 MiB fp32.
// Floor analysis (R10): every byte transits LTS on store + ~80% again on
// L2->DRAM drain => ~480MB LTS traffic / ~12TB/s cap ~= 40us. All structural
// variants (R2/R5/R7/R8) sit on this plateau; R10 (v8 stores) regressed via
// lost occupancy+store-MLP. This is the best-timed config (R2).

#define N_  8
#define G_  8
#define OG_ 16
#define DX_ 256
#define DY_ 256
#define PT  16   // p-rows per block

__global__ __launch_bounds__(256, 8) void scvc_kernel(
    const float* __restrict__ x,   // (N, G, DX)
    const float* __restrict__ y,   // (N, G, DY)
    const float* __restrict__ C,   // (G, OG)
    const float* __restrict__ wA,  // (G, OG, 2)
    const float* __restrict__ wB,  // (G, OG, 2)
    float* __restrict__ out)       // (N, G*OG, DX, DY)
{
    __shared__ float sy[DY_];
    __shared__ float sb[DY_];

    const int b  = blockIdx.x;
    const int pt = b & 15;            // DX_/PT = 16 tiles
    const int o  = (b >> 4) & 15;     // OG_ = 16
    const int g  = (b >> 8) & 7;      // G_  = 8
    const int n  = b >> 11;           // N_  = 8

    const int tid = threadIdx.x;
    const int ng = n * G_ + g;
    const int go = g * OG_ + o;

    const float* __restrict__ yrow = y + ng * DY_;
    const float* __restrict__ xrow = x + ng * DX_;

    const float wB0 = wB[go * 2 + 0];
    const float wB1 = wB[go * 2 + 1];
    const float wA0 = wA[go * 2 + 0];
    const float wA1 = wA[go * 2 + 1];
    const float Cgo = C[go];

    // Stage y row; compute b[q] once per block.
    sy[tid] = yrow[tid];
    __syncthreads();
    {
        const float yl = (tid > 0)       ? sy[tid - 1] : 0.0f;
        const float yr = (tid < DY_ - 1) ? sy[tid + 1] : 0.0f;
        sb[tid] = wB0 * yl + wB1 * yr;
    }
    __syncthreads();

    // Thread layout: r = row-within-4, c = float4 column (64 per row).
    const int r = tid >> 6;
    const int c = tid & 63;

    const float4 yv = reinterpret_cast<const float4*>(sy)[c];
    const float4 bv = reinterpret_cast<const float4*>(sb)[c];

    float* __restrict__ obase =
        out + ((size_t)ng * OG_ + o) * (size_t)(DX_ * DY_);

    #pragma unroll
    for (int it = 0; it < PT / 4; ++it) {
        const int p = pt * PT + it * 4 + r;
        const float xp  = xrow[p];
        const float xl  = (p > 0)        ? xrow[p - 1] : 0.0f;
        const float xr2 = (p < DX_ - 1)  ? xrow[p + 1] : 0.0f;
        const float ap  = wA0 * xl + wA1 * xr2;
        const float s   = Cgo * xp;

        float4 v;
        v.x = fmaf(s, yv.x, ap + bv.x);
        v.y = fmaf(s, yv.y, ap + bv.y);
        v.z = fmaf(s, yv.z, ap + bv.z);
        v.w = fmaf(s, yv.w, ap + bv.w);

        // Streaming store: write-once output, bypass L2 persistence.
        __stcs(reinterpret_cast<float4*>(obase + (size_t)p * DY_) + c, v);
    }
}

extern "C" void kernel_launch(void* const* d_in, const int* in_sizes, int n_in,
                              void* d_out, int out_size)
{
    const float* x  = (const float*)d_in[0];
    const float* y  = (const float*)d_in[1];
    const float* C  = (const float*)d_in[2];
    const float* wA = (const float*)d_in[3];
    const float* wB = (const float*)d_in[4];
    float* out = (float*)d_out;

    const int nblocks = N_ * G_ * OG_ * (DX_ / PT);  // 16384
    scvc_kernel<<<nblocks, 256>>>(x, y, C, wA, wB, out);
}